// round 4
// baseline (speedup 1.0000x reference)
#include <cuda_runtime.h>
#include <math.h>
#include <stdint.h>

#define MTOT 131072
#define TPB  128
#define TOK  128
#define NBLK (MTOT / TOK)

#define XHS 132   // x|h tile row stride (floats)
#define WS  72    // packed K=64 weight row stride
#define FCS 136   // packed K=128 weight row stride

// smem float offsets
#define SW_OFF    0
#define SXH_OFF   9792
#define SGATE_OFF 26688
#define SMEMF     27840   // 111,360 B -> 2 CTAs/SM

// packed-weight global offsets (floats)
#define GW_FC   0
#define GW_GRU  9792
#define GW_E1   37440
#define GW_E2   74304
#define GW_TOT  92736

__device__ __align__(16) float g_wp[GW_TOT];

__device__ __forceinline__ float f2tf_f(float f) {
    uint32_t u; asm("cvt.rna.tf32.f32 %0, %1;" : "=r"(u) : "f"(f));
    return __uint_as_float(u);
}
__device__ __forceinline__ float sig_(float v) { return 1.0f / (1.0f + __expf(-v)); }
__device__ __forceinline__ int packpos(int k) {
    return ((k >> 3) << 3) + ((k & 3) << 1) + ((k >> 2) & 1);
}

__device__ __forceinline__ void mma8(float* d,
    uint32_t a0, uint32_t a1, uint32_t a2, uint32_t a3, uint32_t b0, uint32_t b1)
{
    asm volatile(
        "mma.sync.aligned.m16n8k8.row.col.f32.tf32.tf32.f32 "
        "{%0,%1,%2,%3}, {%4,%5,%6,%7}, {%8,%9}, {%0,%1,%2,%3};"
        : "+f"(d[0]), "+f"(d[1]), "+f"(d[2]), "+f"(d[3])
        : "r"(a0), "r"(a1), "r"(a2), "r"(a3), "r"(b0), "r"(b1));
}

// two m16 stripes (rows +0..15 and +16..31)
#define LOAD_A8(ptr, stride)                                            \
    uint32_t a0 = __float_as_uint((ptr)[tig]);                          \
    uint32_t a2 = __float_as_uint((ptr)[tig + 4]);                      \
    uint32_t a1 = __float_as_uint((ptr)[8 * (stride) + tig]);           \
    uint32_t a3 = __float_as_uint((ptr)[8 * (stride) + tig + 4]);       \
    uint32_t a4 = __float_as_uint((ptr)[16 * (stride) + tig]);          \
    uint32_t a6 = __float_as_uint((ptr)[16 * (stride) + tig + 4]);      \
    uint32_t a5 = __float_as_uint((ptr)[24 * (stride) + tig]);          \
    uint32_t a7 = __float_as_uint((ptr)[24 * (stride) + tig + 4]);

#define MMA2(acc, bv)                              \
    mma8((acc)[0], a0, a1, a2, a3, (bv).x, (bv).y); \
    mma8((acc)[1], a4, a5, a6, a7, (bv).x, (bv).y);

// ---------------- prep: pack + tf32-convert all weights once ----------------
__global__ void prep_pack(const float* __restrict__ fc_w, const float* __restrict__ gate_w,
                          const float* __restrict__ w_ih, const float* __restrict__ w_hh,
                          const float* __restrict__ e_w1, const float* __restrict__ e_w2)
{
    int tid = blockIdx.x * blockDim.x + threadIdx.x;
    int nth = gridDim.x * blockDim.x;
    for (int i = tid; i < 64 * 128; i += nth) {
        int j = i >> 7, k = i & 127;
        g_wp[GW_FC + j * FCS + packpos(k)] = f2tf_f(__ldg(fc_w + i));
    }
    for (int i = tid; i < 8 * 128; i += nth) {
        int j = i >> 7, k = i & 127;
        g_wp[GW_FC + (64 + j) * FCS + packpos(k)] = f2tf_f(__ldg(gate_w + i));
    }
    for (int i = tid; i < 192 * 64; i += nth) {
        int R = i >> 6, k = i & 63;
        int c = (R & 63) >> 4, grp = R >> 6, lr = grp * 16 + (R & 15);
        int d = GW_GRU + c * 6912 + lr * WS + packpos(k);
        g_wp[d]        = f2tf_f(__ldg(w_ih + i));
        g_wp[d + 3456] = f2tf_f(__ldg(w_hh + i));
    }
    for (int i = tid; i < 8 * 64 * 64; i += nth) {
        int n = i >> 12, r = (i >> 6) & 63, k = i & 63;
        g_wp[GW_E1 + n * 4608 + r * WS + packpos(k)] = f2tf_f(__ldg(e_w1 + i));
    }
    for (int i = tid; i < 8 * 32 * 64; i += nth) {
        int n = i >> 11, r = (i >> 6) & 31, k = i & 63;
        g_wp[GW_E2 + n * 2304 + r * WS + packpos(k)] = f2tf_f(__ldg(e_w2 + i));
    }
}

// ---------------- main: 4 warps, 32 rows/warp ----------------
__global__ void __launch_bounds__(TPB, 2) msp_main(
    const float* __restrict__ xin,  const float* __restrict__ hin,
    const float* __restrict__ fc_b,
    const float* __restrict__ b_ih, const float* __restrict__ b_hh,
    const float* __restrict__ e_b1, const float* __restrict__ e_b2,
    const float* __restrict__ gate_b,
    float* __restrict__ out)
{
    extern __shared__ float sm[];
    float* s_w    = sm + SW_OFF;
    float* s_xh   = sm + SXH_OFF;
    float* s_gate = sm + SGATE_OFF;

    const int t = threadIdx.x, lane = t & 31, wid = t >> 5;
    const int gid = lane >> 2, tig = lane & 3;
    const int r0 = wid << 5, base = blockIdx.x * TOK;
    const int row0 = r0 + gid;  // stripe rows: row0, +8, +16, +24

    // ---- prologue ----
    {
        const float4* hsrc = (const float4*)hin;
        for (int i = t; i < TOK * 16; i += TPB) {
            int r = i >> 4, c = i & 15;
            *(float4*)(s_xh + r * XHS + 64 + c * 4) = hsrc[(size_t)(base + r) * 16 + c];
        }
        const float4* xsrc = (const float4*)xin;
        for (int i = t; i < TOK * 16; i += TPB) {
            int r = i >> 4, c = i & 15;
            float4 v = xsrc[(size_t)(base + r) * 32 + c];
            v.x = f2tf_f(v.x); v.y = f2tf_f(v.y); v.z = f2tf_f(v.z); v.w = f2tf_f(v.w);
            *(float4*)(s_xh + r * XHS + c * 4) = v;
        }
        const float4* s = (const float4*)(g_wp + GW_FC);
        float4* d = (float4*)s_w;
        for (int i = t; i < 9792 / 4; i += TPB) d[i] = s[i];
    }
    __syncthreads();

    // ---- Stage A ----
    {
        float accF[8][2][4], accG[2][4];
        #pragma unroll
        for (int nt = 0; nt < 8; ++nt) {
            float b0 = __ldg(fc_b + nt * 8 + 2 * tig), b1 = __ldg(fc_b + nt * 8 + 2 * tig + 1);
            #pragma unroll
            for (int s = 0; s < 2; ++s) {
                accF[nt][s][0] = b0; accF[nt][s][1] = b1;
                accF[nt][s][2] = b0; accF[nt][s][3] = b1;
            }
        }
        {
            float g0 = __ldg(gate_b + 2 * tig), g1 = __ldg(gate_b + 2 * tig + 1);
            #pragma unroll
            for (int s = 0; s < 2; ++s) {
                accG[s][0] = g0; accG[s][1] = g1; accG[s][2] = g0; accG[s][3] = g1;
            }
        }
        #pragma unroll
        for (int half = 0; half < 2; ++half) {
            if (half == 1) {
                __syncthreads();
                const float4* xsrc = (const float4*)xin;
                for (int i = t; i < TOK * 16; i += TPB) {
                    int r = i >> 4, c = i & 15;
                    float4 v = xsrc[(size_t)(base + r) * 32 + 16 + c];
                    v.x = f2tf_f(v.x); v.y = f2tf_f(v.y); v.z = f2tf_f(v.z); v.w = f2tf_f(v.w);
                    *(float4*)(s_xh + r * XHS + c * 4) = v;
                }
                __syncthreads();
            }
            #pragma unroll
            for (int ks = 0; ks < 8; ++ks) {
                const float* ap = s_xh + row0 * XHS + ks * 8;
                LOAD_A8(ap, XHS)
                const int kb = half * 64 + ks * 8 + 2 * tig;
                #pragma unroll
                for (int nt = 0; nt < 8; ++nt) {
                    uint2 bv = *(const uint2*)(s_w + (nt * 8 + gid) * FCS + kb);
                    MMA2(accF[nt], bv)
                }
                uint2 gv = *(const uint2*)(s_w + (64 + gid) * FCS + kb);
                MMA2(accG, gv)
            }
        }
        #pragma unroll
        for (int nt = 0; nt < 8; ++nt) {
            int c0 = nt * 8 + 2 * tig;
            #pragma unroll
            for (int s = 0; s < 2; ++s) {
                int ra = row0 + s * 16, rb = ra + 8;
                s_xh[ra * XHS + c0]     = f2tf_f(fmaxf(accF[nt][s][0], 0.f));
                s_xh[ra * XHS + c0 + 1] = f2tf_f(fmaxf(accF[nt][s][1], 0.f));
                s_xh[rb * XHS + c0]     = f2tf_f(fmaxf(accF[nt][s][2], 0.f));
                s_xh[rb * XHS + c0 + 1] = f2tf_f(fmaxf(accF[nt][s][3], 0.f));
            }
        }
        #pragma unroll
        for (int s = 0; s < 2; ++s) {
            int ra = row0 + s * 16, rb = ra + 8;
            s_gate[ra * 9 + 2 * tig]     = sig_(accG[s][0]);
            s_gate[ra * 9 + 2 * tig + 1] = sig_(accG[s][1]);
            s_gate[rb * 9 + 2 * tig]     = sig_(accG[s][2]);
            s_gate[rb * 9 + 2 * tig + 1] = sig_(accG[s][3]);
        }
    }

    // ---- Stage B: GRU, 4 j-chunks of 16 cols ----
    float hpark[48];
    #pragma unroll
    for (int c = 0; c < 4; ++c) {
        __syncthreads();
        {
            const float4* s = (const float4*)(g_wp + GW_GRU + c * 6912);
            float4* d = (float4*)s_w;
            for (int i = t; i < 1728; i += TPB) d[i] = s[i];   // ih+hh chunk [96][72]
        }
        __syncthreads();

        float ar[2][2][4], az[2][2][4], ani[2][2][4], anh[2][2][4];
        #pragma unroll
        for (int t2 = 0; t2 < 2; ++t2) {
            int j0 = c * 16 + t2 * 8 + 2 * tig;
            float v0 = __ldg(b_ih + j0) + __ldg(b_hh + j0);
            float v1 = __ldg(b_ih + j0 + 1) + __ldg(b_hh + j0 + 1);
            float z0 = __ldg(b_ih + 64 + j0) + __ldg(b_hh + 64 + j0);
            float z1 = __ldg(b_ih + 64 + j0 + 1) + __ldg(b_hh + 64 + j0 + 1);
            float n0 = __ldg(b_ih + 128 + j0), n1 = __ldg(b_ih + 128 + j0 + 1);
            float m0 = __ldg(b_hh + 128 + j0), m1 = __ldg(b_hh + 128 + j0 + 1);
            #pragma unroll
            for (int s = 0; s < 2; ++s) {
                ar[t2][s][0] = v0; ar[t2][s][1] = v1; ar[t2][s][2] = v0; ar[t2][s][3] = v1;
                az[t2][s][0] = z0; az[t2][s][1] = z1; az[t2][s][2] = z0; az[t2][s][3] = z1;
                ani[t2][s][0] = n0; ani[t2][s][1] = n1; ani[t2][s][2] = n0; ani[t2][s][3] = n1;
                anh[t2][s][0] = m0; anh[t2][s][1] = m1; anh[t2][s][2] = m0; anh[t2][s][3] = m1;
            }
        }
        // x-part (B rows 0..47 = ih chunk)
        #pragma unroll
        for (int ks = 0; ks < 8; ++ks) {
            const float* ap = s_xh + row0 * XHS + ks * 8;
            LOAD_A8(ap, XHS)
            const int kb = ks * 8 + 2 * tig;
            #pragma unroll
            for (int t2 = 0; t2 < 2; ++t2) {
                uint2 br = *(const uint2*)(s_w + (t2 * 8 + gid) * WS + kb);
                MMA2(ar[t2], br)
                uint2 bz = *(const uint2*)(s_w + (16 + t2 * 8 + gid) * WS + kb);
                MMA2(az[t2], bz)
                uint2 bn = *(const uint2*)(s_w + (32 + t2 * 8 + gid) * WS + kb);
                MMA2(ani[t2], bn)
            }
        }
        // h-part (B rows 48..95 = hh chunk)
        #pragma unroll
        for (int ks = 0; ks < 8; ++ks) {
            const float* ap = s_xh + row0 * XHS + 64 + ks * 8;
            LOAD_A8(ap, XHS)
            const int kb = ks * 8 + 2 * tig;
            #pragma unroll
            for (int t2 = 0; t2 < 2; ++t2) {
                uint2 br = *(const uint2*)(s_w + (48 + t2 * 8 + gid) * WS + kb);
                MMA2(ar[t2], br)
                uint2 bz = *(const uint2*)(s_w + (64 + t2 * 8 + gid) * WS + kb);
                MMA2(az[t2], bz)
                uint2 bn = *(const uint2*)(s_w + (80 + t2 * 8 + gid) * WS + kb);
                MMA2(anh[t2], bn)
            }
        }
        // epilogue
        #pragma unroll
        for (int t2 = 0; t2 < 2; ++t2) {
            #pragma unroll
            for (int s = 0; s < 2; ++s) {
                #pragma unroll
                for (int e = 0; e < 4; ++e) {
                    int row = row0 + s * 16 + ((e & 2) ? 8 : 0);
                    int j = c * 16 + t2 * 8 + 2 * tig + (e & 1);
                    float rr = sig_(ar[t2][s][e]);
                    float zz = sig_(az[t2][s][e]);
                    float nn = tanhf(fmaf(rr, anh[t2][s][e], ani[t2][s][e]));
                    float hp = s_xh[row * XHS + 64 + j];
                    float hh = fmaf(zz, hp - nn, nn);
                    if (c < 3) hpark[c * 16 + t2 * 8 + s * 4 + e] = hh;
                    else       s_xh[row * XHS + 64 + j] = hh;
                }
            }
        }
    }
    #pragma unroll
    for (int c = 0; c < 3; ++c)
        #pragma unroll
        for (int t2 = 0; t2 < 2; ++t2)
            #pragma unroll
            for (int s = 0; s < 2; ++s)
                #pragma unroll
                for (int e = 0; e < 4; ++e) {
                    int row = row0 + s * 16 + ((e & 2) ? 8 : 0);
                    int j = c * 16 + t2 * 8 + 2 * tig + (e & 1);
                    s_xh[row * XHS + 64 + j] = hpark[c * 16 + t2 * 8 + s * 4 + e];
                }
    __syncthreads();

    // ---- h output ----
    {
        float4* hout = (float4*)(out + (size_t)MTOT * 32);
        for (int i = t; i < TOK * 16; i += TPB) {
            int r = i >> 4, c = i & 15;
            hout[(size_t)(base + r) * 16 + c] = *(const float4*)(s_xh + r * XHS + 64 + c * 4);
        }
    }

    // ---- experts ----
    float fq[4][2][4];
    #pragma unroll
    for (int q = 0; q < 4; ++q)
        #pragma unroll
        for (int s = 0; s < 2; ++s)
            { fq[q][s][0] = fq[q][s][1] = fq[q][s][2] = fq[q][s][3] = 0.f; }
    float* eobase = out + (size_t)MTOT * 96;

    #pragma unroll 1
    for (int n = 0; n < 8; ++n) {
        __syncthreads();
        {
            const float4* s1 = (const float4*)(g_wp + GW_E1 + n * 4608);
            float4* d1 = (float4*)s_w;
            for (int i = t; i < 1152; i += TPB) d1[i] = s1[i];
            const float4* s2 = (const float4*)(g_wp + GW_E2 + n * 2304);
            float4* d2 = (float4*)(s_w + 64 * WS);
            for (int i = t; i < 576; i += TPB) d2[i] = s2[i];
        }
        __syncthreads();

        float acc1[8][2][4];
        #pragma unroll
        for (int nt = 0; nt < 8; ++nt) {
            float b0 = __ldg(e_b1 + n * 64 + nt * 8 + 2 * tig);
            float b1 = __ldg(e_b1 + n * 64 + nt * 8 + 2 * tig + 1);
            #pragma unroll
            for (int s = 0; s < 2; ++s) {
                acc1[nt][s][0] = b0; acc1[nt][s][1] = b1;
                acc1[nt][s][2] = b0; acc1[nt][s][3] = b1;
            }
        }
        #pragma unroll
        for (int ks = 0; ks < 8; ++ks) {
            const float* ap = s_xh + row0 * XHS + 64 + ks * 8;   // h raw
            LOAD_A8(ap, XHS)
            const int kb = ks * 8 + 2 * tig;
            #pragma unroll
            for (int nt = 0; nt < 8; ++nt) {
                uint2 bv = *(const uint2*)(s_w + (nt * 8 + gid) * WS + kb);
                MMA2(acc1[nt], bv)
            }
        }
        __syncwarp();
        #pragma unroll
        for (int nt = 0; nt < 8; ++nt) {   // relu(h1) RNA -> cols 0..63
            int c0 = nt * 8 + 2 * tig;
            #pragma unroll
            for (int s = 0; s < 2; ++s) {
                int ra = row0 + s * 16, rb = ra + 8;
                s_xh[ra * XHS + c0]     = f2tf_f(fmaxf(acc1[nt][s][0], 0.f));
                s_xh[ra * XHS + c0 + 1] = f2tf_f(fmaxf(acc1[nt][s][1], 0.f));
                s_xh[rb * XHS + c0]     = f2tf_f(fmaxf(acc1[nt][s][2], 0.f));
                s_xh[rb * XHS + c0 + 1] = f2tf_f(fmaxf(acc1[nt][s][3], 0.f));
            }
        }
        __syncwarp();

        float acc2[4][2][4];
        #pragma unroll
        for (int nt = 0; nt < 4; ++nt) {
            float b0 = __ldg(e_b2 + n * 32 + nt * 8 + 2 * tig);
            float b1 = __ldg(e_b2 + n * 32 + nt * 8 + 2 * tig + 1);
            #pragma unroll
            for (int s = 0; s < 2; ++s) {
                acc2[nt][s][0] = b0; acc2[nt][s][1] = b1;
                acc2[nt][s][2] = b0; acc2[nt][s][3] = b1;
            }
        }
        #pragma unroll
        for (int ks = 0; ks < 8; ++ks) {
            const float* ap = s_xh + row0 * XHS + ks * 8;        // h1 tf32
            LOAD_A8(ap, XHS)
            const int kb = ks * 8 + 2 * tig;
            #pragma unroll
            for (int nt = 0; nt < 4; ++nt) {
                uint2 bv = *(const uint2*)(s_w + (64 + nt * 8 + gid) * WS + kb);
                MMA2(acc2[nt], bv)
            }
        }
        #pragma unroll
        for (int s = 0; s < 2; ++s) {
            int ra = row0 + s * 16, rb = ra + 8;
            float w0 = s_gate[ra * 9 + n], w1 = s_gate[rb * 9 + n];
            #pragma unroll
            for (int nt = 0; nt < 4; ++nt) {
                fq[nt][s][0] = fmaf(acc2[nt][s][0], w0, fq[nt][s][0]);
                fq[nt][s][1] = fmaf(acc2[nt][s][1], w0, fq[nt][s][1]);
                fq[nt][s][2] = fmaf(acc2[nt][s][2], w1, fq[nt][s][2]);
                fq[nt][s][3] = fmaf(acc2[nt][s][3], w1, fq[nt][s][3]);
                int c0 = n * 32 + nt * 8 + 2 * tig;
                *(float2*)(eobase + (size_t)(base + ra) * 256 + c0) =
                    make_float2(acc2[nt][s][0], acc2[nt][s][1]);
                *(float2*)(eobase + (size_t)(base + rb) * 256 + c0) =
                    make_float2(acc2[nt][s][2], acc2[nt][s][3]);
            }
        }
    }

    // ---- final_q ----
    #pragma unroll
    for (int s = 0; s < 2; ++s) {
        int ra = row0 + s * 16, rb = ra + 8;
        #pragma unroll
        for (int nt = 0; nt < 4; ++nt) {
            int c0 = nt * 8 + 2 * tig;
            *(float2*)(out + (size_t)(base + ra) * 32 + c0) =
                make_float2(fq[nt][s][0] * 0.125f, fq[nt][s][1] * 0.125f);
            *(float2*)(out + (size_t)(base + rb) * 32 + c0) =
                make_float2(fq[nt][s][2] * 0.125f, fq[nt][s][3] * 0.125f);
        }
    }
}

extern "C" void kernel_launch(void* const* d_in, const int* in_sizes, int n_in,
                              void* d_out, int out_size) {
    (void)in_sizes; (void)n_in; (void)out_size;
    prep_pack<<<128, 256>>>(
        (const float*)d_in[2],  (const float*)d_in[12],
        (const float*)d_in[4],  (const float*)d_in[5],
        (const float*)d_in[8],  (const float*)d_in[10]);
    cudaFuncSetAttribute(msp_main, cudaFuncAttributeMaxDynamicSharedMemorySize, SMEMF * 4);
    msp_main<<<NBLK, TPB, SMEMF * 4>>>(
        (const float*)d_in[0],  (const float*)d_in[1],
        (const float*)d_in[3],
        (const float*)d_in[6],  (const float*)d_in[7],
        (const float*)d_in[9],  (const float*)d_in[11],
        (const float*)d_in[13],
        (float*)d_out);
}

// round 5
// speedup vs baseline: 1.8399x; 1.8399x over previous
#include <cuda_runtime.h>
#include <math.h>
#include <stdint.h>

#define MTOT 131072
#define TPB  256
#define TOK  128
#define NBLK (MTOT / TOK)

#define XHS 132   // x|h tile row stride (floats)
#define WS  72    // packed K=64 weight row stride
#define FCS 136   // packed K=128 weight row stride

// smem float offsets
#define SW_OFF    0         // 9792 floats = ping-pong 2 x 4896 (buf0 = +0, buf1 = +4896)
#define SXH_OFF   9792
#define SGATE_OFF 26688
#define SMEMF     27840     // 111,360 B -> 2 CTAs/SM

#define BUF1 4896

// packed-weight global offsets (floats)
#define GW_FC   0
#define GW_GRU  9792        // per chunk c: ih at c*6912, hh at c*6912+3456 (48 rows x 72 each)
#define GW_E1   37440       // per expert: 64 x 72 = 4608
#define GW_E2   74304       // per expert: 32 x 72 = 2304
#define GW_TOT  92736

__device__ __align__(16) float g_wp[GW_TOT];

__device__ __forceinline__ float f2tf_f(float f) {
    uint32_t u; asm("cvt.rna.tf32.f32 %0, %1;" : "=r"(u) : "f"(f));
    return __uint_as_float(u);
}
__device__ __forceinline__ float sig_(float v) { return 1.0f / (1.0f + __expf(-v)); }
__device__ __forceinline__ int packpos(int k) {
    return ((k >> 3) << 3) + ((k & 3) << 1) + ((k >> 2) & 1);
}

__device__ __forceinline__ void cp16(float* dst, const float* src) {
    uint32_t d = (uint32_t)__cvta_generic_to_shared(dst);
    asm volatile("cp.async.cg.shared.global [%0], [%1], 16;" :: "r"(d), "l"(src));
}
__device__ __forceinline__ void stage_async(float* dst, const float* src, int n, int t) {
    for (int i = t * 4; i < n; i += TPB * 4) cp16(dst + i, src + i);
}
#define CP_COMMIT asm volatile("cp.async.commit_group;")
#define CP_WAIT0  asm volatile("cp.async.wait_group 0;")

__device__ __forceinline__ void mma8(float* d,
    uint32_t a0, uint32_t a1, uint32_t a2, uint32_t a3, uint32_t b0, uint32_t b1)
{
    asm volatile(
        "mma.sync.aligned.m16n8k8.row.col.f32.tf32.tf32.f32 "
        "{%0,%1,%2,%3}, {%4,%5,%6,%7}, {%8,%9}, {%0,%1,%2,%3};"
        : "+f"(d[0]), "+f"(d[1]), "+f"(d[2]), "+f"(d[3])
        : "r"(a0), "r"(a1), "r"(a2), "r"(a3), "r"(b0), "r"(b1));
}

#define LOAD_A(ptr, stride)                                        \
    uint32_t a0 = __float_as_uint((ptr)[tig]);                     \
    uint32_t a2 = __float_as_uint((ptr)[tig + 4]);                 \
    uint32_t a1 = __float_as_uint((ptr)[8 * (stride) + tig]);      \
    uint32_t a3 = __float_as_uint((ptr)[8 * (stride) + tig + 4]);

// ---------------- prep: pack + tf32-convert all weights once ----------------
__global__ void prep_pack(const float* __restrict__ fc_w, const float* __restrict__ gate_w,
                          const float* __restrict__ w_ih, const float* __restrict__ w_hh,
                          const float* __restrict__ e_w1, const float* __restrict__ e_w2)
{
    int tid = blockIdx.x * blockDim.x + threadIdx.x;
    int nth = gridDim.x * blockDim.x;
    for (int i = tid; i < 64 * 128; i += nth) {
        int j = i >> 7, k = i & 127;
        g_wp[GW_FC + j * FCS + packpos(k)] = f2tf_f(__ldg(fc_w + i));
    }
    for (int i = tid; i < 8 * 128; i += nth) {
        int j = i >> 7, k = i & 127;
        g_wp[GW_FC + (64 + j) * FCS + packpos(k)] = f2tf_f(__ldg(gate_w + i));
    }
    for (int i = tid; i < 192 * 64; i += nth) {
        int R = i >> 6, k = i & 63;
        int c = (R & 63) >> 4, grp = R >> 6, lr = grp * 16 + (R & 15);
        int d = GW_GRU + c * 6912 + lr * WS + packpos(k);
        g_wp[d]        = f2tf_f(__ldg(w_ih + i));
        g_wp[d + 3456] = f2tf_f(__ldg(w_hh + i));
    }
    for (int i = tid; i < 8 * 64 * 64; i += nth) {
        int n = i >> 12, r = (i >> 6) & 63, k = i & 63;
        g_wp[GW_E1 + n * 4608 + r * WS + packpos(k)] = f2tf_f(__ldg(e_w1 + i));
    }
    for (int i = tid; i < 8 * 32 * 64; i += nth) {
        int n = i >> 11, r = (i >> 6) & 31, k = i & 63;
        g_wp[GW_E2 + n * 2304 + r * WS + packpos(k)] = f2tf_f(__ldg(e_w2 + i));
    }
}

// ---------------- main: 8 warps, 16 rows/warp, pipelined weight staging ----------------
__global__ void __launch_bounds__(TPB, 2) msp_main(
    const float* __restrict__ xin,  const float* __restrict__ hin,
    const float* __restrict__ fc_b,
    const float* __restrict__ b_ih, const float* __restrict__ b_hh,
    const float* __restrict__ e_b1, const float* __restrict__ e_b2,
    const float* __restrict__ gate_b,
    float* __restrict__ out)
{
    extern __shared__ float sm[];
    float* s_w    = sm + SW_OFF;      // buf0; buf1 = s_w + BUF1
    float* s_xh   = sm + SXH_OFF;
    float* s_gate = sm + SGATE_OFF;

    const int t = threadIdx.x, lane = t & 31, wid = t >> 5;
    const int gid = lane >> 2, tig = lane & 3;
    const int r0 = wid << 4, base = blockIdx.x * TOK;
    const int row0 = r0 + gid, row1 = row0 + 8;

    // ---- prologue: cp.async h_in + stage-A weights; regular loads for x (needs cvt) ----
    stage_async(s_w, g_wp + GW_FC, 9792, t);
    for (int i = t; i < TOK * 16; i += TPB) {
        int r = i >> 4, c = i & 15;
        cp16(s_xh + r * XHS + 64 + c * 4, hin + (size_t)(base + r) * 64 + c * 4);
    }
    CP_COMMIT;
    {
        const float4* xsrc = (const float4*)xin;
        for (int i = t; i < TOK * 16; i += TPB) {
            int r = i >> 4, c = i & 15;
            float4 v = xsrc[(size_t)(base + r) * 32 + c];
            v.x = f2tf_f(v.x); v.y = f2tf_f(v.y); v.z = f2tf_f(v.z); v.w = f2tf_f(v.w);
            *(float4*)(s_xh + r * XHS + c * 4) = v;
        }
    }
    CP_WAIT0;
    __syncthreads();

    // ---- Stage A: x = relu(x_in @ fc_w^T + b), gate pre-act ----
    {
        float accF[8][4], accG[4];
        #pragma unroll
        for (int nt = 0; nt < 8; ++nt) {
            float b0 = __ldg(fc_b + nt * 8 + 2 * tig), b1 = __ldg(fc_b + nt * 8 + 2 * tig + 1);
            accF[nt][0] = b0; accF[nt][1] = b1; accF[nt][2] = b0; accF[nt][3] = b1;
        }
        {
            float g0 = __ldg(gate_b + 2 * tig), g1 = __ldg(gate_b + 2 * tig + 1);
            accG[0] = g0; accG[1] = g1; accG[2] = g0; accG[3] = g1;
        }
        #pragma unroll
        for (int half = 0; half < 2; ++half) {
            if (half == 1) {
                __syncthreads();
                const float4* xsrc = (const float4*)xin;
                for (int i = t; i < TOK * 16; i += TPB) {
                    int r = i >> 4, c = i & 15;
                    float4 v = xsrc[(size_t)(base + r) * 32 + 16 + c];
                    v.x = f2tf_f(v.x); v.y = f2tf_f(v.y); v.z = f2tf_f(v.z); v.w = f2tf_f(v.w);
                    *(float4*)(s_xh + r * XHS + c * 4) = v;
                }
                __syncthreads();
            }
            #pragma unroll
            for (int ks = 0; ks < 8; ++ks) {
                const float* ap = s_xh + row0 * XHS + ks * 8;
                LOAD_A(ap, XHS)
                const int kb = half * 64 + ks * 8 + 2 * tig;
                #pragma unroll
                for (int nt = 0; nt < 8; ++nt) {
                    uint2 bv = *(const uint2*)(s_w + (nt * 8 + gid) * FCS + kb);
                    mma8(accF[nt], a0, a1, a2, a3, bv.x, bv.y);
                }
                uint2 gv = *(const uint2*)(s_w + (64 + gid) * FCS + kb);
                mma8(accG, a0, a1, a2, a3, gv.x, gv.y);
            }
        }
        #pragma unroll
        for (int nt = 0; nt < 8; ++nt) {
            int c0 = nt * 8 + 2 * tig;
            s_xh[row0 * XHS + c0]     = f2tf_f(fmaxf(accF[nt][0], 0.f));
            s_xh[row0 * XHS + c0 + 1] = f2tf_f(fmaxf(accF[nt][1], 0.f));
            s_xh[row1 * XHS + c0]     = f2tf_f(fmaxf(accF[nt][2], 0.f));
            s_xh[row1 * XHS + c0 + 1] = f2tf_f(fmaxf(accF[nt][3], 0.f));
        }
        s_gate[row0 * 9 + 2 * tig]     = sig_(accG[0]);
        s_gate[row0 * 9 + 2 * tig + 1] = sig_(accG[1]);
        s_gate[row1 * 9 + 2 * tig]     = sig_(accG[2]);
        s_gate[row1 * 9 + 2 * tig + 1] = sig_(accG[3]);
    }
    __syncthreads();   // stage-A weight reads done; s_w free

    // ---- GRU pipeline: 8 stages (ih/hh x 4 chunks), ping-pong buf0/buf1 ----
    stage_async(s_w, g_wp + GW_GRU, 3456, t);   // ih chunk 0 -> buf0 (only exposed load)
    CP_COMMIT;
    CP_WAIT0;
    __syncthreads();

    float hpark[24];
    #pragma unroll 1
    for (int c = 0; c < 4; ++c) {
        // stage 2c: compute x-part from buf0; prefetch hh chunk c -> buf1
        stage_async(s_w + BUF1, g_wp + GW_GRU + c * 6912 + 3456, 3456, t);
        CP_COMMIT;

        float ar[2][4], az[2][4], ani[2][4], anh[2][4];
        #pragma unroll
        for (int t2 = 0; t2 < 2; ++t2) {
            int j0 = c * 16 + t2 * 8 + 2 * tig;
            float v0 = __ldg(b_ih + j0) + __ldg(b_hh + j0);
            float v1 = __ldg(b_ih + j0 + 1) + __ldg(b_hh + j0 + 1);
            ar[t2][0] = v0; ar[t2][1] = v1; ar[t2][2] = v0; ar[t2][3] = v1;
            float z0 = __ldg(b_ih + 64 + j0) + __ldg(b_hh + 64 + j0);
            float z1 = __ldg(b_ih + 64 + j0 + 1) + __ldg(b_hh + 64 + j0 + 1);
            az[t2][0] = z0; az[t2][1] = z1; az[t2][2] = z0; az[t2][3] = z1;
            float n0 = __ldg(b_ih + 128 + j0), n1 = __ldg(b_ih + 128 + j0 + 1);
            ani[t2][0] = n0; ani[t2][1] = n1; ani[t2][2] = n0; ani[t2][3] = n1;
            float m0 = __ldg(b_hh + 128 + j0), m1 = __ldg(b_hh + 128 + j0 + 1);
            anh[t2][0] = m0; anh[t2][1] = m1; anh[t2][2] = m0; anh[t2][3] = m1;
        }
        #pragma unroll
        for (int ks = 0; ks < 8; ++ks) {
            const float* ap = s_xh + row0 * XHS + ks * 8;      // A = x
            LOAD_A(ap, XHS)
            const int kb = ks * 8 + 2 * tig;
            #pragma unroll
            for (int t2 = 0; t2 < 2; ++t2) {
                uint2 br = *(const uint2*)(s_w + (t2 * 8 + gid) * WS + kb);
                mma8(ar[t2], a0, a1, a2, a3, br.x, br.y);
                uint2 bz = *(const uint2*)(s_w + (16 + t2 * 8 + gid) * WS + kb);
                mma8(az[t2], a0, a1, a2, a3, bz.x, bz.y);
                uint2 bn = *(const uint2*)(s_w + (32 + t2 * 8 + gid) * WS + kb);
                mma8(ani[t2], a0, a1, a2, a3, bn.x, bn.y);
            }
        }
        CP_WAIT0;
        __syncthreads();

        // stage 2c+1: compute h-part from buf1; prefetch next ih (or E1(0)) -> buf0
        if (c < 3) stage_async(s_w, g_wp + GW_GRU + (c + 1) * 6912, 3456, t);
        else       stage_async(s_w, g_wp + GW_E1, 4608, t);
        CP_COMMIT;

        #pragma unroll
        for (int ks = 0; ks < 8; ++ks) {
            const float* ap = s_xh + row0 * XHS + 64 + ks * 8;  // A = h_in
            LOAD_A(ap, XHS)
            const int kb = ks * 8 + 2 * tig;
            #pragma unroll
            for (int t2 = 0; t2 < 2; ++t2) {
                uint2 br = *(const uint2*)(s_w + BUF1 + (t2 * 8 + gid) * WS + kb);
                mma8(ar[t2], a0, a1, a2, a3, br.x, br.y);
                uint2 bz = *(const uint2*)(s_w + BUF1 + (16 + t2 * 8 + gid) * WS + kb);
                mma8(az[t2], a0, a1, a2, a3, bz.x, bz.y);
                uint2 bn = *(const uint2*)(s_w + BUF1 + (32 + t2 * 8 + gid) * WS + kb);
                mma8(anh[t2], a0, a1, a2, a3, bn.x, bn.y);
            }
        }
        // epilogue: chunks 0..2 park h_new; chunk 3 writes + flushes park
        #pragma unroll
        for (int t2 = 0; t2 < 2; ++t2) {
            #pragma unroll
            for (int e = 0; e < 4; ++e) {
                int row = (e & 2) ? row1 : row0;
                int j = c * 16 + t2 * 8 + 2 * tig + (e & 1);
                float rr = sig_(ar[t2][e]);
                float zz = sig_(az[t2][e]);
                float nn = tanhf(fmaf(rr, anh[t2][e], ani[t2][e]));
                float hp = s_xh[row * XHS + 64 + j];
                float hh = fmaf(zz, hp - nn, nn);
                if (c < 3) hpark[c * 8 + t2 * 4 + e] = hh;
                else       s_xh[row * XHS + 64 + j] = hh;
            }
        }
        if (c == 3) {
            #pragma unroll
            for (int cc = 0; cc < 3; ++cc)
                #pragma unroll
                for (int t2 = 0; t2 < 2; ++t2)
                    #pragma unroll
                    for (int e = 0; e < 4; ++e) {
                        int row = (e & 2) ? row1 : row0;
                        int j = cc * 16 + t2 * 8 + 2 * tig + (e & 1);
                        s_xh[row * XHS + 64 + j] = hpark[cc * 8 + t2 * 4 + e];
                    }
        }
        CP_WAIT0;
        __syncthreads();
    }

    // ---- h output (coalesced; h visible after pipeline sync) ----
    {
        float4* hout = (float4*)(out + (size_t)MTOT * 32);
        for (int i = t; i < TOK * 16; i += TPB) {
            int r = i >> 4, c = i & 15;
            hout[(size_t)(base + r) * 16 + c] = *(const float4*)(s_xh + r * XHS + 64 + c * 4);
        }
    }

    // ---- expert pipeline: 16 stages (E1/E2 x 8), E1 in buf0, E2 in buf1 ----
    float fq[4][4];
    #pragma unroll
    for (int q = 0; q < 4; ++q) { fq[q][0] = fq[q][1] = fq[q][2] = fq[q][3] = 0.f; }
    float* eobase = out + (size_t)MTOT * 96;

    #pragma unroll 1
    for (int n = 0; n < 8; ++n) {
        // stage E1(n) compute from buf0; prefetch E2(n) -> buf1
        stage_async(s_w + BUF1, g_wp + GW_E2 + n * 2304, 2304, t);
        CP_COMMIT;

        float acc1[8][4];
        #pragma unroll
        for (int nt = 0; nt < 8; ++nt) {
            float b0 = __ldg(e_b1 + n * 64 + nt * 8 + 2 * tig);
            float b1 = __ldg(e_b1 + n * 64 + nt * 8 + 2 * tig + 1);
            acc1[nt][0] = b0; acc1[nt][1] = b1; acc1[nt][2] = b0; acc1[nt][3] = b1;
        }
        #pragma unroll
        for (int ks = 0; ks < 8; ++ks) {
            const float* ap = s_xh + row0 * XHS + 64 + ks * 8;   // A = h (raw)
            LOAD_A(ap, XHS)
            const int kb = ks * 8 + 2 * tig;
            #pragma unroll
            for (int nt = 0; nt < 8; ++nt) {
                uint2 bv = *(const uint2*)(s_w + (nt * 8 + gid) * WS + kb);
                mma8(acc1[nt], a0, a1, a2, a3, bv.x, bv.y);
            }
        }
        __syncwarp();
        #pragma unroll
        for (int nt = 0; nt < 8; ++nt) {   // relu(h1) RNA -> cols 0..63 (warp-local)
            int c0 = nt * 8 + 2 * tig;
            s_xh[row0 * XHS + c0]     = f2tf_f(fmaxf(acc1[nt][0], 0.f));
            s_xh[row0 * XHS + c0 + 1] = f2tf_f(fmaxf(acc1[nt][1], 0.f));
            s_xh[row1 * XHS + c0]     = f2tf_f(fmaxf(acc1[nt][2], 0.f));
            s_xh[row1 * XHS + c0 + 1] = f2tf_f(fmaxf(acc1[nt][3], 0.f));
        }
        __syncwarp();
        CP_WAIT0;
        __syncthreads();

        // stage E2(n) compute from buf1; prefetch E1(n+1) -> buf0
        if (n < 7) stage_async(s_w, g_wp + GW_E1 + (n + 1) * 4608, 4608, t);
        CP_COMMIT;

        float acc2[4][4];
        #pragma unroll
        for (int nt = 0; nt < 4; ++nt) {
            float b0 = __ldg(e_b2 + n * 32 + nt * 8 + 2 * tig);
            float b1 = __ldg(e_b2 + n * 32 + nt * 8 + 2 * tig + 1);
            acc2[nt][0] = b0; acc2[nt][1] = b1; acc2[nt][2] = b0; acc2[nt][3] = b1;
        }
        #pragma unroll
        for (int ks = 0; ks < 8; ++ks) {
            const float* ap = s_xh + row0 * XHS + ks * 8;        // A = h1 (tf32)
            LOAD_A(ap, XHS)
            const int kb = ks * 8 + 2 * tig;
            #pragma unroll
            for (int nt = 0; nt < 4; ++nt) {
                uint2 bv = *(const uint2*)(s_w + BUF1 + (nt * 8 + gid) * WS + kb);
                mma8(acc2[nt], a0, a1, a2, a3, bv.x, bv.y);
            }
        }
        float w0 = s_gate[row0 * 9 + n], w1 = s_gate[row1 * 9 + n];
        #pragma unroll
        for (int nt = 0; nt < 4; ++nt) {
            fq[nt][0] = fmaf(acc2[nt][0], w0, fq[nt][0]);
            fq[nt][1] = fmaf(acc2[nt][1], w0, fq[nt][1]);
            fq[nt][2] = fmaf(acc2[nt][2], w1, fq[nt][2]);
            fq[nt][3] = fmaf(acc2[nt][3], w1, fq[nt][3]);
            int c0 = n * 32 + nt * 8 + 2 * tig;
            *(float2*)(eobase + (size_t)(base + row0) * 256 + c0) =
                make_float2(acc2[nt][0], acc2[nt][1]);
            *(float2*)(eobase + (size_t)(base + row1) * 256 + c0) =
                make_float2(acc2[nt][2], acc2[nt][3]);
        }
        CP_WAIT0;
        __syncthreads();
    }

    // ---- final_q ----
    #pragma unroll
    for (int nt = 0; nt < 4; ++nt) {
        int c0 = nt * 8 + 2 * tig;
        *(float2*)(out + (size_t)(base + row0) * 32 + c0) =
            make_float2(fq[nt][0] * 0.125f, fq[nt][1] * 0.125f);
        *(float2*)(out + (size_t)(base + row1) * 32 + c0) =
            make_float2(fq[nt][2] * 0.125f, fq[nt][3] * 0.125f);
    }
}

extern "C" void kernel_launch(void* const* d_in, const int* in_sizes, int n_in,
                              void* d_out, int out_size) {
    (void)in_sizes; (void)n_in; (void)out_size;
    prep_pack<<<128, 256>>>(
        (const float*)d_in[2],  (const float*)d_in[12],
        (const float*)d_in[4],  (const float*)d_in[5],
        (const float*)d_in[8],  (const float*)d_in[10]);
    cudaFuncSetAttribute(msp_main, cudaFuncAttributeMaxDynamicSharedMemorySize, SMEMF * 4);
    msp_main<<<NBLK, TPB, SMEMF * 4>>>(
        (const float*)d_in[0],  (const float*)d_in[1],
        (const float*)d_in[3],
        (const float*)d_in[6],  (const float*)d_in[7],
        (const float*)d_in[9],  (const float*)d_in[11],
        (const float*)d_in[13],
        (float*)d_out);
}

// round 6
// speedup vs baseline: 1.9126x; 1.0395x over previous
#include <cuda_runtime.h>
#include <math.h>
#include <stdint.h>

#define MTOT 131072
#define TPB  256
#define TOK  128
#define NBLK (MTOT / TOK)

#define XHS 132   // x|h tile row stride (floats)
#define WS  72    // packed K=64 weight row stride
#define FCS 136   // packed K=128 weight row stride

// smem float offsets
#define SW_OFF    0         // ping-pong 2 x 4896
#define SXH_OFF   9792
#define SGATE_OFF 26688
#define SMEMF     27840     // 111,360 B -> 2 CTAs/SM

#define BUF1 4896

// packed-weight global offsets (floats)
#define GW_FC   0
#define GW_GRU  9792
#define GW_E1   37440
#define GW_E2   74304
#define GW_TOT  92736

__device__ __align__(16) float g_wp[GW_TOT];

__device__ __forceinline__ float f2tf_f(float f) {
    uint32_t u; asm("cvt.rna.tf32.f32 %0, %1;" : "=r"(u) : "f"(f));
    return __uint_as_float(u);
}
__device__ __forceinline__ float sig_(float v) { return 1.0f / (1.0f + __expf(-v)); }
__device__ __forceinline__ int packpos(int k) {
    return ((k >> 3) << 3) + ((k & 3) << 1) + ((k >> 2) & 1);
}

__device__ __forceinline__ void cp16(float* dst, const float* src) {
    uint32_t d = (uint32_t)__cvta_generic_to_shared(dst);
    asm volatile("cp.async.cg.shared.global [%0], [%1], 16;" :: "r"(d), "l"(src));
}
__device__ __forceinline__ void stage_async(float* dst, const float* src, int n, int t) {
    for (int i = t * 4; i < n; i += TPB * 4) cp16(dst + i, src + i);
}
#define CP_COMMIT asm volatile("cp.async.commit_group;")
#define CP_WAIT0  asm volatile("cp.async.wait_group 0;")
#define PAIR_BAR  asm volatile("bar.sync %0, 64;" :: "r"(p + 1) : "memory")

__device__ __forceinline__ void mma8(float* d,
    uint32_t a0, uint32_t a1, uint32_t a2, uint32_t a3, uint32_t b0, uint32_t b1)
{
    asm volatile(
        "mma.sync.aligned.m16n8k8.row.col.f32.tf32.tf32.f32 "
        "{%0,%1,%2,%3}, {%4,%5,%6,%7}, {%8,%9}, {%0,%1,%2,%3};"
        : "+f"(d[0]), "+f"(d[1]), "+f"(d[2]), "+f"(d[3])
        : "r"(a0), "r"(a1), "r"(a2), "r"(a3), "r"(b0), "r"(b1));
}

// A-fragments for TWO m16 stripes (rows +0..15 and +16..31 of the pair stripe)
#define LOAD_A8(ptr, stride)                                            \
    uint32_t a0 = __float_as_uint((ptr)[tig]);                          \
    uint32_t a2 = __float_as_uint((ptr)[tig + 4]);                      \
    uint32_t a1 = __float_as_uint((ptr)[8 * (stride) + tig]);           \
    uint32_t a3 = __float_as_uint((ptr)[8 * (stride) + tig + 4]);       \
    uint32_t a4 = __float_as_uint((ptr)[16 * (stride) + tig]);          \
    uint32_t a6 = __float_as_uint((ptr)[16 * (stride) + tig + 4]);      \
    uint32_t a5 = __float_as_uint((ptr)[24 * (stride) + tig]);          \
    uint32_t a7 = __float_as_uint((ptr)[24 * (stride) + tig + 4]);

#define MMA2(acc, bv)                                   \
    mma8((acc)[0], a0, a1, a2, a3, (bv).x, (bv).y);     \
    mma8((acc)[1], a4, a5, a6, a7, (bv).x, (bv).y);

// ---------------- prep: pack + tf32-convert all weights once ----------------
__global__ void prep_pack(const float* __restrict__ fc_w, const float* __restrict__ gate_w,
                          const float* __restrict__ w_ih, const float* __restrict__ w_hh,
                          const float* __restrict__ e_w1, const float* __restrict__ e_w2)
{
    int tid = blockIdx.x * blockDim.x + threadIdx.x;
    int nth = gridDim.x * blockDim.x;
    for (int i = tid; i < 64 * 128; i += nth) {
        int j = i >> 7, k = i & 127;
        g_wp[GW_FC + j * FCS + packpos(k)] = f2tf_f(__ldg(fc_w + i));
    }
    for (int i = tid; i < 8 * 128; i += nth) {
        int j = i >> 7, k = i & 127;
        g_wp[GW_FC + (64 + j) * FCS + packpos(k)] = f2tf_f(__ldg(gate_w + i));
    }
    for (int i = tid; i < 192 * 64; i += nth) {
        int R = i >> 6, k = i & 63;
        int c = (R & 63) >> 4, grp = R >> 6, lr = grp * 16 + (R & 15);
        int d = GW_GRU + c * 6912 + lr * WS + packpos(k);
        g_wp[d]        = f2tf_f(__ldg(w_ih + i));
        g_wp[d + 3456] = f2tf_f(__ldg(w_hh + i));
    }
    for (int i = tid; i < 8 * 64 * 64; i += nth) {
        int n = i >> 12, r = (i >> 6) & 63, k = i & 63;
        g_wp[GW_E1 + n * 4608 + r * WS + packpos(k)] = f2tf_f(__ldg(e_w1 + i));
    }
    for (int i = tid; i < 8 * 32 * 64; i += nth) {
        int n = i >> 11, r = (i >> 6) & 31, k = i & 63;
        g_wp[GW_E2 + n * 2304 + r * WS + packpos(k)] = f2tf_f(__ldg(e_w2 + i));
    }
}

// ---------------- main: 8 warps, paired on 32-row stripes, N split per pair ----------------
__global__ void __launch_bounds__(TPB, 2) msp_main(
    const float* __restrict__ xin,  const float* __restrict__ hin,
    const float* __restrict__ fc_b,
    const float* __restrict__ b_ih, const float* __restrict__ b_hh,
    const float* __restrict__ e_b1, const float* __restrict__ e_b2,
    const float* __restrict__ gate_b,
    float* __restrict__ out)
{
    extern __shared__ float sm[];
    float* s_w    = sm + SW_OFF;
    float* s_xh   = sm + SXH_OFF;
    float* s_gate = sm + SGATE_OFF;

    const int t = threadIdx.x, lane = t & 31, wid = t >> 5;
    const int gid = lane >> 2, tig = lane & 3;
    const int p = wid >> 1, half = wid & 1;
    const int r0 = p << 5, base = blockIdx.x * TOK;
    const int row0 = r0 + gid;   // stripe rows: row0, +8, +16, +24

    // ---- prologue ----
    stage_async(s_w, g_wp + GW_FC, 9792, t);
    for (int i = t; i < TOK * 16; i += TPB) {
        int r = i >> 4, c = i & 15;
        cp16(s_xh + r * XHS + 64 + c * 4, hin + (size_t)(base + r) * 64 + c * 4);
    }
    CP_COMMIT;
    {
        const float4* xsrc = (const float4*)xin;
        for (int i = t; i < TOK * 16; i += TPB) {
            int r = i >> 4, c = i & 15;
            float4 v = xsrc[(size_t)(base + r) * 32 + c];
            v.x = f2tf_f(v.x); v.y = f2tf_f(v.y); v.z = f2tf_f(v.z); v.w = f2tf_f(v.w);
            *(float4*)(s_xh + r * XHS + c * 4) = v;
        }
    }
    CP_WAIT0;
    __syncthreads();

    // ---- Stage A: x = relu(x_in @ fc_w^T + b); half1 also computes gate ----
    {
        float accF[4][2][4], accG[2][4];
        #pragma unroll
        for (int nt = 0; nt < 4; ++nt) {
            int cb = half * 32 + nt * 8 + 2 * tig;
            float b0 = __ldg(fc_b + cb), b1 = __ldg(fc_b + cb + 1);
            #pragma unroll
            for (int s = 0; s < 2; ++s) {
                accF[nt][s][0] = b0; accF[nt][s][1] = b1;
                accF[nt][s][2] = b0; accF[nt][s][3] = b1;
            }
        }
        {
            float g0 = __ldg(gate_b + 2 * tig), g1 = __ldg(gate_b + 2 * tig + 1);
            #pragma unroll
            for (int s = 0; s < 2; ++s) {
                accG[s][0] = g0; accG[s][1] = g1; accG[s][2] = g0; accG[s][3] = g1;
            }
        }
        #pragma unroll
        for (int kh = 0; kh < 2; ++kh) {
            if (kh == 1) {
                __syncthreads();
                const float4* xsrc = (const float4*)xin;
                for (int i = t; i < TOK * 16; i += TPB) {
                    int r = i >> 4, c = i & 15;
                    float4 v = xsrc[(size_t)(base + r) * 32 + 16 + c];
                    v.x = f2tf_f(v.x); v.y = f2tf_f(v.y); v.z = f2tf_f(v.z); v.w = f2tf_f(v.w);
                    *(float4*)(s_xh + r * XHS + c * 4) = v;
                }
                __syncthreads();
            }
            #pragma unroll
            for (int ks = 0; ks < 8; ++ks) {
                const float* ap = s_xh + row0 * XHS + ks * 8;
                LOAD_A8(ap, XHS)
                const int kb = kh * 64 + ks * 8 + 2 * tig;
                #pragma unroll
                for (int nt = 0; nt < 4; ++nt) {
                    uint2 bv = *(const uint2*)(s_w + (half * 32 + nt * 8 + gid) * FCS + kb);
                    MMA2(accF[nt], bv)
                }
                if (half) {
                    uint2 gv = *(const uint2*)(s_w + (64 + gid) * FCS + kb);
                    MMA2(accG, gv)
                }
            }
        }
        PAIR_BAR;   // partner done reading x_in rows of this stripe before overwrite
        #pragma unroll
        for (int nt = 0; nt < 4; ++nt) {
            int c0 = half * 32 + nt * 8 + 2 * tig;
            #pragma unroll
            for (int s = 0; s < 2; ++s) {
                int ra = row0 + s * 16, rb = ra + 8;
                s_xh[ra * XHS + c0]     = f2tf_f(fmaxf(accF[nt][s][0], 0.f));
                s_xh[ra * XHS + c0 + 1] = f2tf_f(fmaxf(accF[nt][s][1], 0.f));
                s_xh[rb * XHS + c0]     = f2tf_f(fmaxf(accF[nt][s][2], 0.f));
                s_xh[rb * XHS + c0 + 1] = f2tf_f(fmaxf(accF[nt][s][3], 0.f));
            }
        }
        if (half) {
            #pragma unroll
            for (int s = 0; s < 2; ++s) {
                int ra = row0 + s * 16, rb = ra + 8;
                s_gate[ra * 9 + 2 * tig]     = sig_(accG[s][0]);
                s_gate[ra * 9 + 2 * tig + 1] = sig_(accG[s][1]);
                s_gate[rb * 9 + 2 * tig]     = sig_(accG[s][2]);
                s_gate[rb * 9 + 2 * tig + 1] = sig_(accG[s][3]);
            }
        }
    }
    __syncthreads();   // stage-A weight reads done; s_w free

    // ---- GRU pipeline: 8 stages (ih/hh x 4 chunks) ----
    stage_async(s_w, g_wp + GW_GRU, 3456, t);
    CP_COMMIT;
    CP_WAIT0;
    __syncthreads();

    float hpark[24];
    #pragma unroll 1
    for (int c = 0; c < 4; ++c) {
        stage_async(s_w + BUF1, g_wp + GW_GRU + c * 6912 + 3456, 3456, t);
        CP_COMMIT;

        float ar[2][4], az[2][4], ani[2][4], anh[2][4];
        {
            int j0 = c * 16 + half * 8 + 2 * tig;
            float v0 = __ldg(b_ih + j0) + __ldg(b_hh + j0);
            float v1 = __ldg(b_ih + j0 + 1) + __ldg(b_hh + j0 + 1);
            float z0 = __ldg(b_ih + 64 + j0) + __ldg(b_hh + 64 + j0);
            float z1 = __ldg(b_ih + 64 + j0 + 1) + __ldg(b_hh + 64 + j0 + 1);
            float n0 = __ldg(b_ih + 128 + j0), n1 = __ldg(b_ih + 128 + j0 + 1);
            float m0 = __ldg(b_hh + 128 + j0), m1 = __ldg(b_hh + 128 + j0 + 1);
            #pragma unroll
            for (int s = 0; s < 2; ++s) {
                ar[s][0] = v0; ar[s][1] = v1; ar[s][2] = v0; ar[s][3] = v1;
                az[s][0] = z0; az[s][1] = z1; az[s][2] = z0; az[s][3] = z1;
                ani[s][0] = n0; ani[s][1] = n1; ani[s][2] = n0; ani[s][3] = n1;
                anh[s][0] = m0; anh[s][1] = m1; anh[s][2] = m0; anh[s][3] = m1;
            }
        }
        // x-part: B rows = [r:0..15][z:16..31][n:32..47], this warp's 8-j slice
        #pragma unroll
        for (int ks = 0; ks < 8; ++ks) {
            const float* ap = s_xh + row0 * XHS + ks * 8;
            LOAD_A8(ap, XHS)
            const int kb = ks * 8 + 2 * tig;
            uint2 br = *(const uint2*)(s_w + (half * 8 + gid) * WS + kb);
            MMA2(ar, br)
            uint2 bz = *(const uint2*)(s_w + (16 + half * 8 + gid) * WS + kb);
            MMA2(az, bz)
            uint2 bn = *(const uint2*)(s_w + (32 + half * 8 + gid) * WS + kb);
            MMA2(ani, bn)
        }
        CP_WAIT0;
        __syncthreads();

        if (c < 3) stage_async(s_w, g_wp + GW_GRU + (c + 1) * 6912, 3456, t);
        else       stage_async(s_w, g_wp + GW_E1, 4608, t);
        CP_COMMIT;

        // h-part
        #pragma unroll
        for (int ks = 0; ks < 8; ++ks) {
            const float* ap = s_xh + row0 * XHS + 64 + ks * 8;
            LOAD_A8(ap, XHS)
            const int kb = ks * 8 + 2 * tig;
            uint2 br = *(const uint2*)(s_w + BUF1 + (half * 8 + gid) * WS + kb);
            MMA2(ar, br)
            uint2 bz = *(const uint2*)(s_w + BUF1 + (16 + half * 8 + gid) * WS + kb);
            MMA2(az, bz)
            uint2 bn = *(const uint2*)(s_w + BUF1 + (32 + half * 8 + gid) * WS + kb);
            MMA2(anh, bn)
        }
        if (c == 3) { PAIR_BAR; }  // partner must finish h-part A reads before h writes
        #pragma unroll
        for (int s = 0; s < 2; ++s) {
            #pragma unroll
            for (int e = 0; e < 4; ++e) {
                int row = row0 + s * 16 + ((e & 2) ? 8 : 0);
                int j = c * 16 + half * 8 + 2 * tig + (e & 1);
                float rr = sig_(ar[s][e]);
                float zz = sig_(az[s][e]);
                float nn = tanhf(fmaf(rr, anh[s][e], ani[s][e]));
                float hp = s_xh[row * XHS + 64 + j];
                float hh = fmaf(zz, hp - nn, nn);
                if (c < 3) hpark[c * 8 + s * 4 + e] = hh;
                else       s_xh[row * XHS + 64 + j] = hh;
            }
        }
        if (c == 3) {
            #pragma unroll
            for (int cc = 0; cc < 3; ++cc)
                #pragma unroll
                for (int s = 0; s < 2; ++s)
                    #pragma unroll
                    for (int e = 0; e < 4; ++e) {
                        int row = row0 + s * 16 + ((e & 2) ? 8 : 0);
                        int j = cc * 16 + half * 8 + 2 * tig + (e & 1);
                        s_xh[row * XHS + 64 + j] = hpark[cc * 8 + s * 4 + e];
                    }
        }
        CP_WAIT0;
        __syncthreads();
    }

    // ---- h output (coalesced) ----
    {
        float4* hout = (float4*)(out + (size_t)MTOT * 32);
        for (int i = t; i < TOK * 16; i += TPB) {
            int r = i >> 4, c = i & 15;
            hout[(size_t)(base + r) * 16 + c] = *(const float4*)(s_xh + r * XHS + 64 + c * 4);
        }
    }

    // ---- experts: 16 pipelined stages ----
    float fq[2][2][4];
    #pragma unroll
    for (int q = 0; q < 2; ++q)
        #pragma unroll
        for (int s = 0; s < 2; ++s)
            { fq[q][s][0] = fq[q][s][1] = fq[q][s][2] = fq[q][s][3] = 0.f; }
    float* eobase = out + (size_t)MTOT * 96;

    #pragma unroll 1
    for (int n = 0; n < 8; ++n) {
        stage_async(s_w + BUF1, g_wp + GW_E2 + n * 2304, 2304, t);
        CP_COMMIT;

        float acc1[4][2][4];
        #pragma unroll
        for (int nt = 0; nt < 4; ++nt) {
            int cb = n * 64 + half * 32 + nt * 8 + 2 * tig;
            float b0 = __ldg(e_b1 + cb), b1 = __ldg(e_b1 + cb + 1);
            #pragma unroll
            for (int s = 0; s < 2; ++s) {
                acc1[nt][s][0] = b0; acc1[nt][s][1] = b1;
                acc1[nt][s][2] = b0; acc1[nt][s][3] = b1;
            }
        }
        #pragma unroll
        for (int ks = 0; ks < 8; ++ks) {
            const float* ap = s_xh + row0 * XHS + 64 + ks * 8;   // A = h (raw)
            LOAD_A8(ap, XHS)
            const int kb = ks * 8 + 2 * tig;
            #pragma unroll
            for (int nt = 0; nt < 4; ++nt) {
                uint2 bv = *(const uint2*)(s_w + (half * 32 + nt * 8 + gid) * WS + kb);
                MMA2(acc1[nt], bv)
            }
        }
        #pragma unroll
        for (int nt = 0; nt < 4; ++nt) {   // relu(h1) RNA -> warp's 32 cols
            int c0 = half * 32 + nt * 8 + 2 * tig;
            #pragma unroll
            for (int s = 0; s < 2; ++s) {
                int ra = row0 + s * 16, rb = ra + 8;
                s_xh[ra * XHS + c0]     = f2tf_f(fmaxf(acc1[nt][s][0], 0.f));
                s_xh[ra * XHS + c0 + 1] = f2tf_f(fmaxf(acc1[nt][s][1], 0.f));
                s_xh[rb * XHS + c0]     = f2tf_f(fmaxf(acc1[nt][s][2], 0.f));
                s_xh[rb * XHS + c0 + 1] = f2tf_f(fmaxf(acc1[nt][s][3], 0.f));
            }
        }
        PAIR_BAR;   // pair's h1 halves visible before E2 reads full h1
        CP_WAIT0;
        __syncthreads();

        if (n < 7) stage_async(s_w, g_wp + GW_E1 + (n + 1) * 4608, 4608, t);
        CP_COMMIT;

        float acc2[2][2][4];
        #pragma unroll
        for (int nt = 0; nt < 2; ++nt) {
            int cb = n * 32 + half * 16 + nt * 8 + 2 * tig;
            float b0 = __ldg(e_b2 + cb), b1 = __ldg(e_b2 + cb + 1);
            #pragma unroll
            for (int s = 0; s < 2; ++s) {
                acc2[nt][s][0] = b0; acc2[nt][s][1] = b1;
                acc2[nt][s][2] = b0; acc2[nt][s][3] = b1;
            }
        }
        #pragma unroll
        for (int ks = 0; ks < 8; ++ks) {
            const float* ap = s_xh + row0 * XHS + ks * 8;        // A = h1 (tf32)
            LOAD_A8(ap, XHS)
            const int kb = ks * 8 + 2 * tig;
            #pragma unroll
            for (int nt = 0; nt < 2; ++nt) {
                uint2 bv = *(const uint2*)(s_w + BUF1 + (half * 16 + nt * 8 + gid) * WS + kb);
                MMA2(acc2[nt], bv)
            }
        }
        #pragma unroll
        for (int s = 0; s < 2; ++s) {
            int ra = row0 + s * 16, rb = ra + 8;
            float w0 = s_gate[ra * 9 + n], w1 = s_gate[rb * 9 + n];
            #pragma unroll
            for (int nt = 0; nt < 2; ++nt) {
                fq[nt][s][0] = fmaf(acc2[nt][s][0], w0, fq[nt][s][0]);
                fq[nt][s][1] = fmaf(acc2[nt][s][1], w0, fq[nt][s][1]);
                fq[nt][s][2] = fmaf(acc2[nt][s][2], w1, fq[nt][s][2]);
                fq[nt][s][3] = fmaf(acc2[nt][s][3], w1, fq[nt][s][3]);
                int c0 = n * 32 + half * 16 + nt * 8 + 2 * tig;
                *(float2*)(eobase + (size_t)(base + ra) * 256 + c0) =
                    make_float2(acc2[nt][s][0], acc2[nt][s][1]);
                *(float2*)(eobase + (size_t)(base + rb) * 256 + c0) =
                    make_float2(acc2[nt][s][2], acc2[nt][s][3]);
            }
        }
        CP_WAIT0;
        __syncthreads();
    }

    // ---- final_q ----
    #pragma unroll
    for (int s = 0; s < 2; ++s) {
        int ra = row0 + s * 16, rb = ra + 8;
        #pragma unroll
        for (int nt = 0; nt < 2; ++nt) {
            int c0 = half * 16 + nt * 8 + 2 * tig;
            *(float2*)(out + (size_t)(base + ra) * 32 + c0) =
                make_float2(fq[nt][s][0] * 0.125f, fq[nt][s][1] * 0.125f);
            *(float2*)(out + (size_t)(base + rb) * 32 + c0) =
                make_float2(fq[nt][s][2] * 0.125f, fq[nt][s][3] * 0.125f);
        }
    }
}

extern "C" void kernel_launch(void* const* d_in, const int* in_sizes, int n_in,
                              void* d_out, int out_size) {
    (void)in_sizes; (void)n_in; (void)out_size;
    prep_pack<<<128, 256>>>(
        (const float*)d_in[2],  (const float*)d_in[12],
        (const float*)d_in[4],  (const float*)d_in[5],
        (const float*)d_in[8],  (const float*)d_in[10]);
    cudaFuncSetAttribute(msp_main, cudaFuncAttributeMaxDynamicSharedMemorySize, SMEMF * 4);
    msp_main<<<NBLK, TPB, SMEMF * 4>>>(
        (const float*)d_in[0],  (const float*)d_in[1],
        (const float*)d_in[3],
        (const float*)d_in[6],  (const float*)d_in[7],
        (const float*)d_in[9],  (const float*)d_in[11],
        (const float*)d_in[13],
        (float*)d_out);
}